// round 8
// baseline (speedup 1.0000x reference)
#include <cuda_runtime.h>
#include <cstdint>

#define BB 1024
#define TT 128
#define KK 128
#define START_TAG 126
#define STOP_TAG  127
#define NEG_INF __int_as_float(0xff800000)
#define PADK 40                      // padded 32-float quarter (bank-spread + 16B align)

// Scratch: partition history (64 MB) + transposed transitions.
__device__ float g_part[(size_t)BB * TT * KK];
__device__ float g_trT[KK * KK];

__global__ void transpose_trans(const float* __restrict__ trans) {
    int idx = blockIdx.x * blockDim.x + threadIdx.x;   // 0..16383
    int p = idx >> 7, c = idx & 127;
    g_trT[c * KK + p] = trans[idx];
}

__device__ __forceinline__ unsigned sortable(float f) {
    unsigned u = __float_as_uint(f);
    return u ^ ((unsigned)((int)u >> 31) | 0x80000000u);
}

__global__ __launch_bounds__(512, 2)
void viterbi_fused(const float* __restrict__ feats,
                   const float* __restrict__ trans,
                   const void*  __restrict__ masks,
                   float* __restrict__ out)
{
    extern __shared__ float strT[];                  // 64 KB, backtrace phase
    __shared__ __align__(16) float pbuf[2][4 * PADK];
    __shared__ float s_rv[4];
    __shared__ int   s_ri[4];
    __shared__ int   s_ptr;

    const int b    = blockIdx.x;
    const int tid  = threadIdx.x;
    const int w    = tid >> 5;                       // warp 0..15
    const int lane = tid & 31;
    const int s    = lane >> 2;                      // cur-sub 0..7
    const int pq   = lane & 3;                       // prev quarter 0..3
    const int c    = w * 8 + s;                      // this thread's cur tag
    const bool owner = (pq == 0);

    // Transition slice trans[pq*32 + j][c], j=0..31, held in 32 registers.
    float trc[32];
    #pragma unroll
    for (int j = 0; j < 32; ++j)
        trc[j] = trans[(pq * 32 + j) * KK + c];      // coalesced across c

    // Mask dtype sniff (lengths >= 64 so masks[0][1..3] true iff uint8 layout).
    const unsigned char* mu = (const unsigned char*)masks;
    const bool isU8 = (mu[1] | mu[2] | mu[3]) != 0;
    bool mb = false;
    if (tid < TT)
        mb = isU8 ? (mu[(size_t)b * TT + tid] != 0)
                  : (((const int*)masks)[(size_t)b * TT + tid] != 0);
    const int li = __syncthreads_count(mb) - 1;      // last valid index [63,127]

    const float* fb = feats + (size_t)b * TT * KK;
    const int padc = (c >> 5) * PADK + (c & 31);

    // t=0 init: part0[c] = feats[b,0,c] + trans[START,c]
    float myp = 0.f, fq = 0.f;
    if (owner) {
        myp = fb[c] + trans[START_TAG * KK + c];
        pbuf[0][padc] = myp;
        fq = fb[KK + c];                             // prefetch feat t=1
    }
    __syncthreads();

    for (int t = 1; t <= li; ++t) {
        float fnext = 0.f;
        if (owner) {
            const int tn = (t < li) ? t + 1 : li;
            fnext = fb[tn * KK + c];                              // prefetch
            g_part[((size_t)b * TT + (t - 1)) * KK + c] = myp;    // spill history
        }

        const float4* o4 = (const float4*)(pbuf[(t - 1) & 1]) + pq * (PADK / 4);
        float a0 = NEG_INF, a1 = NEG_INF, a2 = NEG_INF, a3 = NEG_INF;
        #pragma unroll
        for (int q = 0; q < 8; ++q) {
            const float4 pv = o4[q];                 // LDS.128, bank-spread via pad
            a0 = fmaxf(a0, pv.x + trc[4 * q + 0]);
            a1 = fmaxf(a1, pv.y + trc[4 * q + 1]);
            a2 = fmaxf(a2, pv.z + trc[4 * q + 2]);
            a3 = fmaxf(a3, pv.w + trc[4 * q + 3]);
        }
        float v = fmaxf(fmaxf(a0, a1), fmaxf(a2, a3));
        v = fmaxf(v, __shfl_xor_sync(0xffffffffu, v, 1));   // combine 4 prev-quarters
        v = fmaxf(v, __shfl_xor_sync(0xffffffffu, v, 2));
        if (owner) {
            myp = v + fq;
            pbuf[t & 1][padc] = myp;
            fq = fnext;
        }
        __syncthreads();
    }

    // Stage transposed transitions into smem for STOP + backtrace.
    {
        const float4* src = (const float4*)g_trT;
        float4* dst = (float4*)strT;
        #pragma unroll
        for (int i = tid; i < KK * KK / 4; i += 512)
            dst[i] = src[i];
    }
    __syncthreads();

    // STOP argmax over prev (first-index tie-break, matches jnp.argmax).
    if (tid < KK) {
        float v = pbuf[li & 1][(tid >> 5) * PADK + (tid & 31)]
                + strT[STOP_TAG * KK + tid];
        unsigned sv = sortable(v);
        unsigned smax = __reduce_max_sync(0xffffffffu, sv);
        unsigned m = __ballot_sync(0xffffffffu, sv == smax);
        int leader = __ffs(m) - 1;
        if ((tid & 31) == leader) { s_rv[tid >> 5] = v; s_ri[tid >> 5] = tid; }
    }
    __syncthreads();
    if (tid == 0) {
        float bv = s_rv[0]; int bi = s_ri[0];
        #pragma unroll
        for (int k = 1; k < 4; ++k)
            if (s_rv[k] > bv || (s_rv[k] == bv && s_ri[k] < bi)) { bv = s_rv[k]; bi = s_ri[k]; }
        out[b] = bv;                                  // path_score
        s_ptr = bi;                                   // best last tag
    }
    __syncthreads();

    // Backtrace: warp 0 only. Recompute each backpointer as a 128-wide argmax
    // over part_hist[j][prev] + trT[ptr][prev]; rows prefetched 2 deep.
    if (tid < 32) {
        const int pointer = s_ptr;
        int ptr = pointer;
        float* dec = out + BB + (size_t)b * TT;
        if (lane == 0) dec[TT - 1] = (float)pointer;

        const float4* prow = (const float4*)(g_part + (size_t)b * TT * KK);
        float4 r_j   = prow[(((TT - 2) * KK) >> 2) + lane];
        float4 r_jm1 = prow[(((TT - 3) * KK) >> 2) + lane];

        for (int j = TT - 2; j >= 0; --j) {
            int jp = j - 2; if (jp < 0) jp = 0;
            float4 r_new = prow[((jp * KK) >> 2) + lane];   // prefetch row j-2

            if (j > li) {
                ptr = 0;                          // masked bp rows are zero
            } else if (j == li) {
                ptr = pointer;                    // bp_all[last_idx] := pointer
            } else {
                const float4 tv = *(const float4*)(strT + ptr * KK + 4 * lane);
                const int base = lane * 4;
                float c0 = r_j.x + tv.x, c1 = r_j.y + tv.y;
                float c2 = r_j.z + tv.z, c3 = r_j.w + tv.w;
                float v = c0; int idx = base;
                if (c1 > v) { v = c1; idx = base + 1; }
                if (c2 > v) { v = c2; idx = base + 2; }
                if (c3 > v) { v = c3; idx = base + 3; }
                unsigned sv = sortable(v);
                unsigned smax = __reduce_max_sync(0xffffffffu, sv);
                unsigned mm = __ballot_sync(0xffffffffu, sv == smax);
                int leader = __ffs(mm) - 1;       // lowest lane = lowest prev
                ptr = __shfl_sync(0xffffffffu, idx, leader);
            }
            if (lane == 0) dec[j] = (float)ptr;
            r_j = r_jm1; r_jm1 = r_new;
        }
    }
}

extern "C" void kernel_launch(void* const* d_in, const int* in_sizes, int n_in,
                              void* d_out, int out_size)
{
    const float* feats = (const float*)d_in[0];
    const float* trans = (const float*)d_in[1];
    const void*  masks = d_in[2];
    float* out = (float*)d_out;

    static bool attr_done = false;
    if (!attr_done) {
        cudaFuncSetAttribute(viterbi_fused,
                             cudaFuncAttributeMaxDynamicSharedMemorySize,
                             KK * KK * (int)sizeof(float));
        attr_done = true;
    }

    transpose_trans<<<KK * KK / 256, 256>>>(trans);
    viterbi_fused<<<BB, 512, KK * KK * sizeof(float)>>>(feats, trans, masks, out);
}

// round 13
// speedup vs baseline: 1.2222x; 1.2222x over previous
#include <cuda_runtime.h>
#include <cstdint>

#define BB 1024
#define TT 128
#define KK 128
#define START_TAG 126
#define STOP_TAG  127
#define NEG_INF __int_as_float(0xff800000)
#define HOFF 72          // float offset of prev-half 1 in pbuf (64 + 8 pad, 16B aligned)

// Scratch: partition history (64 MB) + transposed transitions.
__device__ float g_part[(size_t)BB * TT * KK];
__device__ float g_trT[KK * KK];

__global__ void transpose_trans(const float* __restrict__ trans) {
    int idx = blockIdx.x * blockDim.x + threadIdx.x;   // 0..16383
    int p = idx >> 7, c = idx & 127;
    g_trT[c * KK + p] = trans[idx];
}

__device__ __forceinline__ unsigned sortable(float f) {
    unsigned u = __float_as_uint(f);
    return u ^ ((unsigned)((int)u >> 31) | 0x80000000u);
}
__device__ __forceinline__ int slot(int c) { return c + ((c >> 6) << 3); }

__global__ __launch_bounds__(256, 2)
void viterbi_fused(const float* __restrict__ feats,
                   const float* __restrict__ trans,
                   const void*  __restrict__ masks,
                   float* __restrict__ out)
{
    extern __shared__ float strT[];                  // 64 KB, backtrace phase
    __shared__ __align__(16) float pbuf[2][2 * HOFF];
    __shared__ float s_rv[4];
    __shared__ int   s_ri[4];
    __shared__ int   s_ptr;

    const int b    = blockIdx.x;
    const int tid  = threadIdx.x;
    const int lane = tid & 31;
    const int ph   = lane & 1;                       // prev half: ph*64 .. ph*64+63
    const int sc   = lane >> 1;                      // cur-sub 0..15
    const int c    = (tid >> 5) * 16 + sc;           // this thread's cur tag
    const bool owner = (ph == 0);

    // Transition slice trans[ph*64 + j][c], j=0..63, held in 64 registers.
    float trc[64];
    #pragma unroll
    for (int j = 0; j < 64; ++j)
        trc[j] = trans[(ph * 64 + j) * KK + c];      // coalesced across c

    // Mask dtype sniff (lengths >= 64 so masks[0][1..3] true iff uint8 layout).
    const unsigned char* mu = (const unsigned char*)masks;
    const bool isU8 = (mu[1] | mu[2] | mu[3]) != 0;
    bool mb = false;
    if (tid < TT)
        mb = isU8 ? (mu[(size_t)b * TT + tid] != 0)
                  : (((const int*)masks)[(size_t)b * TT + tid] != 0);
    const int li = __syncthreads_count(mb) - 1;      // last valid index [63,127]

    const float* fb = feats + (size_t)b * TT * KK;
    const int myslot = slot(c);

    // t=0 init: part0[c] = feats[b,0,c] + trans[START,c]
    float myp = 0.f, fq = 0.f;
    if (owner) {
        myp = fb[c] + trans[START_TAG * KK + c];
        pbuf[0][myslot] = myp;
        fq = fb[KK + c];                             // prefetch feat t=1
    }
    __syncthreads();

    for (int t = 1; t <= li; ++t) {
        float fnext = 0.f;
        if (owner) {
            const int tn = (t < li) ? t + 1 : li;
            fnext = fb[tn * KK + c];                              // prefetch
            g_part[((size_t)b * TT + (t - 1)) * KK + c] = myp;    // spill history
        }

        const float4* o4 = (const float4*)(pbuf[(t - 1) & 1] + ph * HOFF);
        float a0 = NEG_INF, a1 = NEG_INF;
        #pragma unroll
        for (int q = 0; q < 16; ++q) {
            const float4 pv = o4[q];                 // LDS.128, 2 bcast addrs/warp
            // chained fmax for FMNMX3 fusion: acc = max3(acc, u, v)
            a0 = fmaxf(fmaxf(a0, pv.x + trc[4 * q + 0]), pv.y + trc[4 * q + 1]);
            a1 = fmaxf(fmaxf(a1, pv.z + trc[4 * q + 2]), pv.w + trc[4 * q + 3]);
        }
        float v = fmaxf(a0, a1);
        v = fmaxf(v, __shfl_xor_sync(0xffffffffu, v, 1));   // combine 2 prev-halves
        if (owner) {
            myp = v + fq;
            pbuf[t & 1][myslot] = myp;
            fq = fnext;
        }
        __syncthreads();
    }

    // Stage transposed transitions into smem for STOP + backtrace.
    {
        const float4* src = (const float4*)g_trT;
        float4* dst = (float4*)strT;
        #pragma unroll
        for (int i = tid; i < KK * KK / 4; i += 256)
            dst[i] = src[i];
    }
    __syncthreads();

    // STOP argmax over prev (first-index tie-break, matches jnp.argmax).
    if (tid < KK) {
        float v = pbuf[li & 1][slot(tid)] + strT[STOP_TAG * KK + tid];
        unsigned sv = sortable(v);
        unsigned smax = __reduce_max_sync(0xffffffffu, sv);
        unsigned m = __ballot_sync(0xffffffffu, sv == smax);
        int leader = __ffs(m) - 1;
        if ((tid & 31) == leader) { s_rv[tid >> 5] = v; s_ri[tid >> 5] = tid; }
    }
    __syncthreads();
    if (tid == 0) {
        float bv = s_rv[0]; int bi = s_ri[0];
        #pragma unroll
        for (int k = 1; k < 4; ++k)
            if (s_rv[k] > bv || (s_rv[k] == bv && s_ri[k] < bi)) { bv = s_rv[k]; bi = s_ri[k]; }
        out[b] = bv;                                  // path_score
        s_ptr = bi;                                   // best last tag
    }
    __syncthreads();

    // Backtrace: warp 0 only. Recompute each backpointer as a 128-wide argmax
    // over part_hist[j][prev] + trT[ptr][prev]; rows prefetched 2 deep.
    if (tid < 32) {
        const int pointer = s_ptr;
        int ptr = pointer;
        float* dec = out + BB + (size_t)b * TT;
        if (lane == 0) dec[TT - 1] = (float)pointer;

        const float4* prow = (const float4*)(g_part + (size_t)b * TT * KK);
        float4 r_j   = prow[(((TT - 2) * KK) >> 2) + lane];
        float4 r_jm1 = prow[(((TT - 3) * KK) >> 2) + lane];

        for (int j = TT - 2; j >= 0; --j) {
            int jp = j - 2; if (jp < 0) jp = 0;
            float4 r_new = prow[((jp * KK) >> 2) + lane];   // prefetch row j-2

            if (j > li) {
                ptr = 0;                          // masked bp rows are zero
            } else if (j == li) {
                ptr = pointer;                    // bp_all[last_idx] := pointer
            } else {
                const float4 tv = *(const float4*)(strT + ptr * KK + 4 * lane);
                const int base = lane * 4;
                float c0 = r_j.x + tv.x, c1 = r_j.y + tv.y;
                float c2 = r_j.z + tv.z, c3 = r_j.w + tv.w;
                float v = c0; int idx = base;
                if (c1 > v) { v = c1; idx = base + 1; }
                if (c2 > v) { v = c2; idx = base + 2; }
                if (c3 > v) { v = c3; idx = base + 3; }
                unsigned sv = sortable(v);
                unsigned smax = __reduce_max_sync(0xffffffffu, sv);
                unsigned mm = __ballot_sync(0xffffffffu, sv == smax);
                int leader = __ffs(mm) - 1;       // lowest lane = lowest prev
                ptr = __shfl_sync(0xffffffffu, idx, leader);
            }
            if (lane == 0) dec[j] = (float)ptr;
            r_j = r_jm1; r_jm1 = r_new;
        }
    }
}

extern "C" void kernel_launch(void* const* d_in, const int* in_sizes, int n_in,
                              void* d_out, int out_size)
{
    const float* feats = (const float*)d_in[0];
    const float* trans = (const float*)d_in[1];
    const void*  masks = d_in[2];
    float* out = (float*)d_out;

    static bool attr_done = false;
    if (!attr_done) {
        cudaFuncSetAttribute(viterbi_fused,
                             cudaFuncAttributeMaxDynamicSharedMemorySize,
                             KK * KK * (int)sizeof(float));
        attr_done = true;
    }

    transpose_trans<<<KK * KK / 256, 256>>>(trans);
    viterbi_fused<<<BB, 256, KK * KK * sizeof(float)>>>(feats, trans, masks, out);
}

// round 15
// speedup vs baseline: 1.5820x; 1.2944x over previous
#include <cuda_runtime.h>
#include <cstdint>

#define BB 1024
#define NB 512           // CTAs; each handles batches (b, b+512)
#define TT 128
#define KK 128
#define START_TAG 126
#define STOP_TAG  127
#define NEG_INF __int_as_float(0xff800000)
#define HOFF 72          // float offset of prev-half 1 in pbuf (64 + 8 pad)

__device__ float g_part[(size_t)BB * TT * KK];
__device__ float g_trT[KK * KK];

__global__ void transpose_trans(const float* __restrict__ trans) {
    int idx = blockIdx.x * blockDim.x + threadIdx.x;
    int p = idx >> 7, c = idx & 127;
    g_trT[c * KK + p] = trans[idx];
}

__device__ __forceinline__ unsigned sortable(float f) {
    unsigned u = __float_as_uint(f);
    return u ^ ((unsigned)((int)u >> 31) | 0x80000000u);
}
__device__ __forceinline__ int slot(int c) { return c + ((c >> 6) << 3); }

__global__ __launch_bounds__(256, 2)
void viterbi_fused(const float* __restrict__ feats,
                   const float* __restrict__ trans,
                   const void*  __restrict__ masks,
                   float* __restrict__ out)
{
    extern __shared__ float strT[];                  // 64 KB, backtrace phase
    __shared__ __align__(16) float pbufA[2][2 * HOFF];
    __shared__ __align__(16) float pbufB[2][2 * HOFF];
    __shared__ float s_rv[8];
    __shared__ int   s_ri[8];
    __shared__ int   s_ptrA, s_ptrB;

    const int bA   = blockIdx.x;
    const int bB   = blockIdx.x + NB;
    const int tid  = threadIdx.x;
    const int lane = tid & 31;
    const int ph   = lane & 1;                       // prev half
    const int c    = (tid >> 5) * 16 + (lane >> 1);  // cur tag
    const bool owner = (ph == 0);

    // Shared transition slice: trans[ph*64 + j][c] — serves BOTH batches.
    float trc[64];
    #pragma unroll
    for (int j = 0; j < 64; ++j)
        trc[j] = trans[(ph * 64 + j) * KK + c];

    // Mask dtype sniff + per-batch lengths (monotone masks).
    const unsigned char* mu = (const unsigned char*)masks;
    const bool isU8 = (mu[1] | mu[2] | mu[3]) != 0;
    bool mbA = false, mbB = false;
    if (tid < TT) {
        mbA = isU8 ? (mu[(size_t)bA * TT + tid] != 0)
                   : (((const int*)masks)[(size_t)bA * TT + tid] != 0);
    } else {
        int t2 = tid - TT;
        mbB = isU8 ? (mu[(size_t)bB * TT + t2] != 0)
                   : (((const int*)masks)[(size_t)bB * TT + t2] != 0);
    }
    const int liA = __syncthreads_count(mbA) - 1;    // in [63,127]
    const int liB = __syncthreads_count(mbB) - 1;
    const int limax = max(liA, liB);

    const float* fbA = feats + (size_t)bA * TT * KK;
    const float* fbB = feats + (size_t)bB * TT * KK;
    float* gA = g_part + (size_t)bA * TT * KK;
    float* gB = g_part + (size_t)bB * TT * KK;
    const int myslot = slot(c);

    // t = 0 init (also spill row 0).
    float mypA = 0.f, mypB = 0.f;
    if (owner) {
        float st = trans[START_TAG * KK + c];
        mypA = fbA[c] + st;
        mypB = fbB[c] + st;
        pbufA[0][myslot] = mypA;
        pbufB[0][myslot] = mypB;
        gA[c] = mypA;
        gB[c] = mypB;
    }
    __syncthreads();

    for (int t = 1; t <= limax; ++t) {
        const bool doA = (t <= liA), doB = (t <= liB);
        float fqA = 0.f, fqB = 0.f;
        if (owner && doA) fqA = fbA[t * KK + c];     // consumed after chains
        if (owner && doB) fqB = fbB[t * KK + c];

        const float4* oA = (const float4*)(pbufA[(t - 1) & 1] + ph * HOFF);
        const float4* oB = (const float4*)(pbufB[(t - 1) & 1] + ph * HOFF);
        float a0 = NEG_INF, a1 = NEG_INF, b0 = NEG_INF, b1 = NEG_INF;
        #pragma unroll
        for (int q = 0; q < 16; ++q) {
            const float4 pA = oA[q];
            const float4 pB = oB[q];
            a0 = fmaxf(fmaxf(a0, pA.x + trc[4 * q + 0]), pA.y + trc[4 * q + 1]);
            a1 = fmaxf(fmaxf(a1, pA.z + trc[4 * q + 2]), pA.w + trc[4 * q + 3]);
            b0 = fmaxf(fmaxf(b0, pB.x + trc[4 * q + 0]), pB.y + trc[4 * q + 1]);
            b1 = fmaxf(fmaxf(b1, pB.z + trc[4 * q + 2]), pB.w + trc[4 * q + 3]);
        }
        float vA = fmaxf(a0, a1);
        float vB = fmaxf(b0, b1);
        vA = fmaxf(vA, __shfl_xor_sync(0xffffffffu, vA, 1));
        vB = fmaxf(vB, __shfl_xor_sync(0xffffffffu, vB, 1));
        if (owner) {
            if (doA) {
                mypA = vA + fqA;
                pbufA[t & 1][myslot] = mypA;
                gA[t * KK + c] = mypA;               // spill history row t
            }
            if (doB) {
                mypB = vB + fqB;
                pbufB[t & 1][myslot] = mypB;
                gB[t * KK + c] = mypB;
            }
        }
        __syncthreads();
    }

    // Stage transposed transitions for STOP + backtrace.
    {
        const float4* src = (const float4*)g_trT;
        float4* dst = (float4*)strT;
        #pragma unroll
        for (int i = tid; i < KK * KK / 4; i += 256)
            dst[i] = src[i];
    }
    __syncthreads();

    // STOP argmax per batch (first-index tie-break). Warps 0-3: A, 4-7: B.
    {
        const int half = tid >> 7;                   // 0 = A, 1 = B
        const int tg   = tid & 127;                  // tag index
        float base = half ? pbufB[liB & 1][slot(tg)] : pbufA[liA & 1][slot(tg)];
        float v = base + strT[STOP_TAG * KK + tg];
        unsigned sv = sortable(v);
        unsigned smax = __reduce_max_sync(0xffffffffu, sv);
        unsigned m = __ballot_sync(0xffffffffu, sv == smax);
        int leader = __ffs(m) - 1;
        if (lane == leader) { s_rv[tid >> 5] = v; s_ri[tid >> 5] = tg; }
    }
    __syncthreads();
    if (tid == 0 || tid == 128) {
        const int o = (tid >> 7) * 4;
        float bv = s_rv[o]; int bi = s_ri[o];
        #pragma unroll
        for (int k = 1; k < 4; ++k)
            if (s_rv[o + k] > bv || (s_rv[o + k] == bv && s_ri[o + k] < bi)) {
                bv = s_rv[o + k]; bi = s_ri[o + k];
            }
        if (tid == 0) { out[bA] = bv; s_ptrA = bi; }
        else          { out[bB] = bv; s_ptrB = bi; }
    }
    __syncthreads();

    // Backtrace: warp 0 -> batch A, warp 1 -> batch B (concurrent).
    if (tid < 64) {
        const int half = tid >> 5;                   // 0 = A, 1 = B
        const int b    = half ? bB : bA;
        const int li   = half ? liB : liA;
        const int pointer = half ? s_ptrB : s_ptrA;
        int ptr = pointer;
        float* dec = out + BB + (size_t)b * TT;
        if (lane == 0) dec[TT - 1] = (float)pointer;

        const float4* prow = (const float4*)(g_part + (size_t)b * TT * KK);
        float4 r_j   = prow[(((TT - 2) * KK) >> 2) + lane];
        float4 r_jm1 = prow[(((TT - 3) * KK) >> 2) + lane];

        for (int j = TT - 2; j >= 0; --j) {
            int jp = j - 2; if (jp < 0) jp = 0;
            float4 r_new = prow[((jp * KK) >> 2) + lane];   // prefetch j-2

            if (j > li) {
                ptr = 0;                          // masked bp rows are zero
            } else if (j == li) {
                ptr = pointer;                    // bp_all[last_idx] := pointer
            } else {
                const float4 tv = *(const float4*)(strT + ptr * KK + 4 * lane);
                const int base = lane * 4;
                float c0 = r_j.x + tv.x, c1 = r_j.y + tv.y;
                float c2 = r_j.z + tv.z, c3 = r_j.w + tv.w;
                float v = c0; int idx = base;
                if (c1 > v) { v = c1; idx = base + 1; }
                if (c2 > v) { v = c2; idx = base + 2; }
                if (c3 > v) { v = c3; idx = base + 3; }
                unsigned sv = sortable(v);
                unsigned smax = __reduce_max_sync(0xffffffffu, sv);
                unsigned mm = __ballot_sync(0xffffffffu, sv == smax);
                int leader = __ffs(mm) - 1;       // lowest lane = lowest prev
                ptr = __shfl_sync(0xffffffffu, idx, leader);
            }
            if (lane == 0) dec[j] = (float)ptr;
            r_j = r_jm1; r_jm1 = r_new;
        }
    }
}

extern "C" void kernel_launch(void* const* d_in, const int* in_sizes, int n_in,
                              void* d_out, int out_size)
{
    const float* feats = (const float*)d_in[0];
    const float* trans = (const float*)d_in[1];
    const void*  masks = d_in[2];
    float* out = (float*)d_out;

    static bool attr_done = false;
    if (!attr_done) {
        cudaFuncSetAttribute(viterbi_fused,
                             cudaFuncAttributeMaxDynamicSharedMemorySize,
                             KK * KK * (int)sizeof(float));
        attr_done = true;
    }

    transpose_trans<<<KK * KK / 256, 256>>>(trans);
    viterbi_fused<<<NB, 256, KK * KK * sizeof(float)>>>(feats, trans, masks, out);
}